// round 10
// baseline (speedup 1.0000x reference)
#include <cuda_runtime.h>
#include <cuda_bf16.h>

// CG solve: X such that M X = RHS, 20 iterations, freeze once rTr <= 1e-10.
// n = 8192 (f32). Dominant cost: 20 streaming reads of the 256 MB matrix.
//
// Structure per iteration (2 launches, both wide):
//   k_matvec(it): stages p_it = r_it + beta*p_{it-1} into smem (beta from exact
//                 scalar sums), writes its slice of p_it to a parity buffer,
//                 computes Ap = M p_it and accumulates pAp[it] via atomics.
//   k_update(it): fully parallel elementwise X += alpha p ; r -= alpha Ap ;
//                 accumulates rTr[it+1] = ||r_new||^2 via per-block atomics.
// No single-block serialized reduction anywhere in the iteration loop.

#define N_MAX 8192
#define CG_NITER 20
#define CG_TOL 1e-10f

// ---- persistent device state (allocation-free scratch) ----
__device__ float g_X[N_MAX];
__device__ float g_r[N_MAX];
__device__ float g_p0[N_MAX];           // p parity buffers: p_it lives in (it&1)
__device__ float g_p1[N_MAX];
__device__ float g_Ap[N_MAX];
__device__ float g_rTr[CG_NITER + 1];   // exact ||r||^2 entering iteration it
__device__ float g_pAp[CG_NITER];

__device__ __forceinline__ float* pbuf(int parity) { return parity ? g_p1 : g_p0; }

// ---- reductions ----
__device__ __forceinline__ float warp_reduce(float v) {
    #pragma unroll
    for (int o = 16; o > 0; o >>= 1) v += __shfl_xor_sync(0xffffffffu, v, o);
    return v;
}

__device__ __forceinline__ float block_reduce(float v) {
    __shared__ float sbuf[32];
    int lane = threadIdx.x & 31;
    int wid  = threadIdx.x >> 5;
    v = warp_reduce(v);
    if (lane == 0) sbuf[wid] = v;
    __syncthreads();
    int nw = (blockDim.x + 31) >> 5;
    v = (threadIdx.x < nw) ? sbuf[threadIdx.x] : 0.0f;
    if (wid == 0) v = warp_reduce(v);
    return v;
}

// ---- kernels ----

// X0 = 0, r0 = RHS, rTr[0] = sum(RHS^2); zero scalar accumulators.
__global__ void k_init_vecs(const float* __restrict__ RHS, int n) {
    int i = blockIdx.x * blockDim.x + threadIdx.x;
    if (blockIdx.x == 0 && threadIdx.x < CG_NITER + 1) {
        g_rTr[threadIdx.x] = 0.0f;
        if (threadIdx.x < CG_NITER) g_pAp[threadIdx.x] = 0.0f;
    }
    float v = 0.0f;
    if (i < n) {
        float rhs = RHS[i];
        g_X[i] = 0.0f;
        g_r[i] = rhs;
        v = rhs * rhs;
    }
    float s = block_reduce(v);
    if (threadIdx.x == 0) atomicAdd(&g_rTr[0], s);
}

// 512 threads = 16 warps, one row per warp. grid = 8192/16 = 512 blocks
// -> 4 blocks/SM (2048 threads, 128 KB smem): exactly one wave, no tail.
// Stages p_it = r + beta*p_old into smem (it=0: p_0 = r), writes own slice
// of p_it to the parity buffer, then streams M with __ldcs.
__global__ void __launch_bounds__(512) k_matvec(const float* __restrict__ M, int n, int it) {
    float rtr = g_rTr[it];
    if (rtr <= CG_TOL) return;          // frozen: skip the 256 MB read entirely

    __shared__ float sp[N_MAX];         // 32 KB
    float4* sp4w = reinterpret_cast<float4*>(sp);
    const float4* r4 = reinterpret_cast<const float4*>(g_r);
    int nq = n >> 2;                    // 2048

    if (it == 0) {
        for (int j = threadIdx.x; j < nq; j += 512) sp4w[j] = r4[j];
    } else {
        float beta = rtr / g_rTr[it - 1];
        const float4* po4 = reinterpret_cast<const float4*>(pbuf((it - 1) & 1));
        for (int j = threadIdx.x; j < nq; j += 512) {
            float4 rv = r4[j];
            float4 pv = po4[j];
            float4 o;
            o.x = fmaf(beta, pv.x, rv.x);
            o.y = fmaf(beta, pv.y, rv.y);
            o.z = fmaf(beta, pv.z, rv.z);
            o.w = fmaf(beta, pv.w, rv.w);
            sp4w[j] = o;
        }
    }
    __syncthreads();

    // persist this block's 16-float slice of p_it (float4 x4, threads 0..3)
    if (threadIdx.x < 4) {
        reinterpret_cast<float4*>(pbuf(it & 1))[blockIdx.x * 4 + threadIdx.x] =
            sp4w[blockIdx.x * 4 + threadIdx.x];
    }

    int lane = threadIdx.x & 31;
    int wid  = threadIdx.x >> 5;        // 0..15
    int row  = blockIdx.x * 16 + wid;

    float a0 = 0.0f, a1 = 0.0f, a2 = 0.0f, a3 = 0.0f;
    {
        const float4* Mrow = reinterpret_cast<const float4*>(M + (size_t)row * n);
        const float4* sp4  = reinterpret_cast<const float4*>(sp);
        #pragma unroll 8
        for (int j = lane; j < nq; j += 32) {
            float4 m  = __ldcs(Mrow + j);   // streaming: no L2 retention for M
            float4 pv = sp4[j];
            a0 = fmaf(m.x, pv.x, a0);
            a1 = fmaf(m.y, pv.y, a1);
            a2 = fmaf(m.z, pv.z, a2);
            a3 = fmaf(m.w, pv.w, a3);
        }
    }
    float acc = (a0 + a1) + (a2 + a3);
    acc = warp_reduce(acc);

    __shared__ float wpart[16];
    if (lane == 0) {
        g_Ap[row] = acc;
        wpart[wid] = sp[row] * acc;         // p[row] * Ap[row]
    }
    __syncthreads();
    if (threadIdx.x == 0) {
        float s = 0.0f;
        #pragma unroll
        for (int w = 0; w < 16; ++w) s += wpart[w];
        atomicAdd(&g_pAp[it], s);
    }
}

// Fully parallel vector update: 8 blocks x 256 threads, one float4 each.
//   alpha = rTr/pAp ; X += alpha p ; r -= alpha Ap ;
//   rTr[it+1] += block-partial ||r_new||^2   (exact sum via atomics)
__global__ void __launch_bounds__(256) k_update(int n, int it) {
    float rtr = g_rTr[it];
    if (rtr <= CG_TOL) return;          // frozen: rTr[it+1] stays 0 -> stays frozen

    float alpha = rtr / g_pAp[it];
    const float4* P4  = reinterpret_cast<const float4*>(pbuf(it & 1));
    const float4* AP4 = reinterpret_cast<const float4*>(g_Ap);
    float4* R4 = reinterpret_cast<float4*>(g_r);
    float4* X4 = reinterpret_cast<float4*>(g_X);

    int q = blockIdx.x * 256 + threadIdx.x;   // 0..2047

    float4 p = P4[q];
    float4 a = AP4[q];
    float4 r = R4[q];
    float4 x = X4[q];

    x.x = fmaf(alpha, p.x, x.x); x.y = fmaf(alpha, p.y, x.y);
    x.z = fmaf(alpha, p.z, x.z); x.w = fmaf(alpha, p.w, x.w);
    X4[q] = x;

    r.x = fmaf(-alpha, a.x, r.x); r.y = fmaf(-alpha, a.y, r.y);
    r.z = fmaf(-alpha, a.z, r.z); r.w = fmaf(-alpha, a.w, r.w);
    R4[q] = r;

    float v = r.x*r.x + r.y*r.y + r.z*r.z + r.w*r.w;
    float s = block_reduce(v);
    if (threadIdx.x == 0) atomicAdd(&g_rTr[it + 1], s);
}

__global__ void k_writeback(float* __restrict__ out, int n) {
    int i = blockIdx.x * blockDim.x + threadIdx.x;
    if (i < n) out[i] = g_X[i];
}

extern "C" void kernel_launch(void* const* d_in, const int* in_sizes, int n_in,
                              void* d_out, int out_size) {
    // metadata order: X [n], M [n*n], RHS [n]
    const float* M   = (const float*)d_in[1];
    const float* RHS = (const float*)d_in[2];
    float* out = (float*)d_out;
    int n = in_sizes[0];

    const int T = 256;
    int vb = (n + T - 1) / T;

    k_init_vecs<<<vb, T>>>(RHS, n);

    int mv_blocks = n / 16;             // 512 blocks, one exact wave
    int up_blocks = (n / 4) / 256;      // 8 blocks
    for (int it = 0; it < CG_NITER; ++it) {
        k_matvec<<<mv_blocks, 512>>>(M, n, it);
        k_update<<<up_blocks, 256>>>(n, it);
    }
    k_writeback<<<vb, T>>>(out, n);
}

// round 13
// speedup vs baseline: 1.0475x; 1.0475x over previous
#include <cuda_runtime.h>
#include <cuda_bf16.h>

// CG solve: X such that M X = RHS, 20 iterations, freeze once rTr <= 1e-10.
// n = 8192 (f32). Dominant cost: 20 streaming reads of the 256 MB matrix.
//
// Structure per iteration (2 launches, both wide):
//   k_matvec(it): stages p_it = r_it + beta*p_{it-1} into smem (beta from exact
//                 scalar sums), writes its slice of p_it to a parity buffer,
//                 computes Ap = M p_it and accumulates pAp[it] via atomics.
//   k_update(it): fully parallel elementwise X += alpha p ; r -= alpha Ap ;
//                 accumulates rTr[it+1] = ||r_new||^2 via per-block atomics.
// k_matvec is pinned to 4 blocks/SM (<=32 regs) so grid=512 is ONE exact wave.

#define N_MAX 8192
#define CG_NITER 20
#define CG_TOL 1e-10f

// ---- persistent device state (allocation-free scratch) ----
__device__ float g_X[N_MAX];
__device__ float g_r[N_MAX];
__device__ float g_p0[N_MAX];           // p parity buffers: p_it lives in (it&1)
__device__ float g_p1[N_MAX];
__device__ float g_Ap[N_MAX];
__device__ float g_rTr[CG_NITER + 1];   // exact ||r||^2 entering iteration it
__device__ float g_pAp[CG_NITER];

__device__ __forceinline__ float* pbuf(int parity) { return parity ? g_p1 : g_p0; }

// ---- reductions ----
__device__ __forceinline__ float warp_reduce(float v) {
    #pragma unroll
    for (int o = 16; o > 0; o >>= 1) v += __shfl_xor_sync(0xffffffffu, v, o);
    return v;
}

__device__ __forceinline__ float block_reduce(float v) {
    __shared__ float sbuf[32];
    int lane = threadIdx.x & 31;
    int wid  = threadIdx.x >> 5;
    v = warp_reduce(v);
    if (lane == 0) sbuf[wid] = v;
    __syncthreads();
    int nw = (blockDim.x + 31) >> 5;
    v = (threadIdx.x < nw) ? sbuf[threadIdx.x] : 0.0f;
    if (wid == 0) v = warp_reduce(v);
    return v;
}

// ---- kernels ----

// X0 = 0, r0 = RHS, rTr[0] = sum(RHS^2); zero scalar accumulators.
__global__ void k_init_vecs(const float* __restrict__ RHS, int n) {
    int i = blockIdx.x * blockDim.x + threadIdx.x;
    if (blockIdx.x == 0 && threadIdx.x < CG_NITER + 1) {
        g_rTr[threadIdx.x] = 0.0f;
        if (threadIdx.x < CG_NITER) g_pAp[threadIdx.x] = 0.0f;
    }
    float v = 0.0f;
    if (i < n) {
        float rhs = RHS[i];
        g_X[i] = 0.0f;
        g_r[i] = rhs;
        v = rhs * rhs;
    }
    float s = block_reduce(v);
    if (threadIdx.x == 0) atomicAdd(&g_rTr[0], s);
}

// 512 threads = 16 warps, one row per warp. grid = 8192/16 = 512 blocks.
// __launch_bounds__(512, 4) pins regs <= 32 -> 4 blocks/SM (2048 threads,
// 128 KB smem): exactly one wave, no tail. Stages p_it = r + beta*p_old into
// smem (it=0: p_0 = r), writes own slice of p_it, then streams M with __ldcs.
__global__ void __launch_bounds__(512, 4) k_matvec(const float* __restrict__ M, int n, int it) {
    float rtr = g_rTr[it];
    if (rtr <= CG_TOL) return;          // frozen: skip the 256 MB read entirely

    __shared__ float sp[N_MAX];         // 32 KB
    float4* sp4w = reinterpret_cast<float4*>(sp);
    const float4* r4 = reinterpret_cast<const float4*>(g_r);
    int nq = n >> 2;                    // 2048

    if (it == 0) {
        for (int j = threadIdx.x; j < nq; j += 512) sp4w[j] = r4[j];
    } else {
        float beta = rtr / g_rTr[it - 1];
        const float4* po4 = reinterpret_cast<const float4*>(pbuf((it - 1) & 1));
        for (int j = threadIdx.x; j < nq; j += 512) {
            float4 rv = r4[j];
            float4 pv = po4[j];
            float4 o;
            o.x = fmaf(beta, pv.x, rv.x);
            o.y = fmaf(beta, pv.y, rv.y);
            o.z = fmaf(beta, pv.z, rv.z);
            o.w = fmaf(beta, pv.w, rv.w);
            sp4w[j] = o;
        }
    }
    __syncthreads();

    // persist this block's 16-float slice of p_it (float4 x4, threads 0..3)
    if (threadIdx.x < 4) {
        reinterpret_cast<float4*>(pbuf(it & 1))[blockIdx.x * 4 + threadIdx.x] =
            sp4w[blockIdx.x * 4 + threadIdx.x];
    }

    int lane = threadIdx.x & 31;
    int wid  = threadIdx.x >> 5;        // 0..15
    int row  = blockIdx.x * 16 + wid;

    float a0 = 0.0f, a1 = 0.0f, a2 = 0.0f, a3 = 0.0f;
    {
        const float4* Mrow = reinterpret_cast<const float4*>(M + (size_t)row * n);
        const float4* sp4  = reinterpret_cast<const float4*>(sp);
        #pragma unroll 8
        for (int j = lane; j < nq; j += 32) {
            float4 m  = __ldcs(Mrow + j);   // streaming: no L2 retention for M
            float4 pv = sp4[j];
            a0 = fmaf(m.x, pv.x, a0);
            a1 = fmaf(m.y, pv.y, a1);
            a2 = fmaf(m.z, pv.z, a2);
            a3 = fmaf(m.w, pv.w, a3);
        }
    }
    float acc = (a0 + a1) + (a2 + a3);
    acc = warp_reduce(acc);

    __shared__ float wpart[16];
    if (lane == 0) {
        g_Ap[row] = acc;
        wpart[wid] = sp[row] * acc;         // p[row] * Ap[row]
    }
    __syncthreads();
    if (threadIdx.x == 0) {
        float s = 0.0f;
        #pragma unroll
        for (int w = 0; w < 16; ++w) s += wpart[w];
        atomicAdd(&g_pAp[it], s);
    }
}

// Fully parallel vector update: 8 blocks x 256 threads, one float4 each.
//   alpha = rTr/pAp ; X += alpha p ; r -= alpha Ap ;
//   rTr[it+1] += block-partial ||r_new||^2   (exact sum via atomics)
__global__ void __launch_bounds__(256) k_update(int n, int it) {
    float rtr = g_rTr[it];
    if (rtr <= CG_TOL) return;          // frozen: rTr[it+1] stays 0 -> stays frozen

    float alpha = rtr / g_pAp[it];
    const float4* P4  = reinterpret_cast<const float4*>(pbuf(it & 1));
    const float4* AP4 = reinterpret_cast<const float4*>(g_Ap);
    float4* R4 = reinterpret_cast<float4*>(g_r);
    float4* X4 = reinterpret_cast<float4*>(g_X);

    int q = blockIdx.x * 256 + threadIdx.x;   // 0..2047

    float4 p = P4[q];
    float4 a = AP4[q];
    float4 r = R4[q];
    float4 x = X4[q];

    x.x = fmaf(alpha, p.x, x.x); x.y = fmaf(alpha, p.y, x.y);
    x.z = fmaf(alpha, p.z, x.z); x.w = fmaf(alpha, p.w, x.w);
    X4[q] = x;

    r.x = fmaf(-alpha, a.x, r.x); r.y = fmaf(-alpha, a.y, r.y);
    r.z = fmaf(-alpha, a.z, r.z); r.w = fmaf(-alpha, a.w, r.w);
    R4[q] = r;

    float v = r.x*r.x + r.y*r.y + r.z*r.z + r.w*r.w;
    float s = block_reduce(v);
    if (threadIdx.x == 0) atomicAdd(&g_rTr[it + 1], s);
}

__global__ void k_writeback(float* __restrict__ out, int n) {
    int i = blockIdx.x * blockDim.x + threadIdx.x;
    if (i < n) out[i] = g_X[i];
}

extern "C" void kernel_launch(void* const* d_in, const int* in_sizes, int n_in,
                              void* d_out, int out_size) {
    // metadata order: X [n], M [n*n], RHS [n]
    const float* M   = (const float*)d_in[1];
    const float* RHS = (const float*)d_in[2];
    float* out = (float*)d_out;
    int n = in_sizes[0];

    const int T = 256;
    int vb = (n + T - 1) / T;

    k_init_vecs<<<vb, T>>>(RHS, n);

    int mv_blocks = n / 16;             // 512 blocks, one exact wave
    int up_blocks = (n / 4) / 256;      // 8 blocks
    for (int it = 0; it < CG_NITER; ++it) {
        k_matvec<<<mv_blocks, 512>>>(M, n, it);
        k_update<<<up_blocks, 256>>>(n, it);
    }
    k_writeback<<<vb, T>>>(out, n);
}

// round 14
// speedup vs baseline: 1.6894x; 1.6128x over previous
#include <cuda_runtime.h>
#include <cuda_bf16.h>

// CG solve via SYMMETRIC matvec: M = A A^T + I is symmetric, so Ap = M p is
// computed from the lower-triangular tiles only -> 53% of the matrix traffic.
// n = 8192, 64x64 grid of 128x128 tiles, 2080 lower tiles.
//
// Per iteration (3 launches):
//   k_matvec_sym: stages p_it = r + beta*p_old slices per block (diag blocks
//                 persist p_it), streams lower tiles; each off-diag tile adds
//                 both T*p_bj (rows) and T^T*p_bi (cols) into g_Ap via atomics.
//   k_dot:        pAp[it] = p . Ap   (8 blocks, exact sum via atomics)
//   k_update:     X += alpha p ; r -= alpha Ap ; rTr[it+1] = ||r_new||^2 ;
//                 zeroes g_Ap for the next iteration.

#define N_MAX 8192
#define TILE 128
#define NBLK (N_MAX / TILE)             // 64 block-rows
#define CG_NITER 20
#define CG_TOL 1e-10f

// ---- persistent device state (allocation-free scratch) ----
__device__ float g_X[N_MAX];
__device__ float g_r[N_MAX];
__device__ float g_p0[N_MAX];           // p parity buffers: p_it lives in (it&1)
__device__ float g_p1[N_MAX];
__device__ float g_Ap[N_MAX];           // zeroed before each matvec
__device__ float g_rTr[CG_NITER + 1];   // exact ||r||^2 entering iteration it
__device__ float g_pAp[CG_NITER];

__device__ __forceinline__ float* pbuf(int parity) { return parity ? g_p1 : g_p0; }

// ---- reductions ----
__device__ __forceinline__ float warp_reduce(float v) {
    #pragma unroll
    for (int o = 16; o > 0; o >>= 1) v += __shfl_xor_sync(0xffffffffu, v, o);
    return v;
}

__device__ __forceinline__ float block_reduce(float v) {
    __shared__ float sbuf[32];
    int lane = threadIdx.x & 31;
    int wid  = threadIdx.x >> 5;
    v = warp_reduce(v);
    if (lane == 0) sbuf[wid] = v;
    __syncthreads();
    int nw = (blockDim.x + 31) >> 5;
    v = (threadIdx.x < nw) ? sbuf[threadIdx.x] : 0.0f;
    if (wid == 0) v = warp_reduce(v);
    return v;
}

// ---- kernels ----

// X0 = 0, r0 = RHS, Ap = 0, rTr[0] = sum(RHS^2); zero scalar accumulators.
__global__ void k_init_vecs(const float* __restrict__ RHS, int n) {
    int i = blockIdx.x * blockDim.x + threadIdx.x;
    if (blockIdx.x == 0 && threadIdx.x < CG_NITER + 1) {
        g_rTr[threadIdx.x] = 0.0f;
        if (threadIdx.x < CG_NITER) g_pAp[threadIdx.x] = 0.0f;
    }
    float v = 0.0f;
    if (i < n) {
        float rhs = RHS[i];
        g_X[i] = 0.0f;
        g_r[i] = rhs;
        g_Ap[i] = 0.0f;
        v = rhs * rhs;
    }
    float s = block_reduce(v);
    if (threadIdx.x == 0) atomicAdd(&g_rTr[0], s);
}

// Symmetric tiled matvec. One block = one 128x128 tile (bi >= bj).
// 256 threads = 8 warps x 16 rows; one warp-LDG.128 covers a full 512B row.
__global__ void __launch_bounds__(256) k_matvec_sym(const float* __restrict__ M, int n, int it) {
    float rtr = g_rTr[it];
    if (rtr <= CG_TOL) return;          // frozen: skip everything

    // decode lower-triangle tile (bi, bj), t = bi*(bi+1)/2 + bj
    int t = blockIdx.x;
    int bi = (int)((sqrtf(8.0f * (float)t + 1.0f) - 1.0f) * 0.5f);
    while ((bi + 1) * (bi + 2) / 2 <= t) bi++;
    while (bi * (bi + 1) / 2 > t) bi--;
    int bj = t - bi * (bi + 1) / 2;

    __shared__ float spi[TILE];          // p slice for block-row bi
    __shared__ float spj[TILE];          // p slice for block-col bj
    __shared__ float yi[TILE];           // row-dot results
    __shared__ float wcol[8][TILE];      // per-warp column partials

    int tx = threadIdx.x;

    // stage p_it = r + beta * p_old for the two slices this tile needs
    {
        float beta = (it == 0) ? 0.0f : rtr / g_rTr[it - 1];
        const float* pold = pbuf((it - 1) & 1);
        if (tx < TILE) {
            int gi = bi * TILE + tx;
            float v = (it == 0) ? g_r[gi] : fmaf(beta, pold[gi], g_r[gi]);
            spi[tx] = v;
            if (bi == bj) pbuf(it & 1)[gi] = v;   // diagonal blocks persist p_it
        } else {
            int j = tx - TILE;
            int gj = bj * TILE + j;
            spj[j] = (it == 0) ? g_r[gj] : fmaf(beta, pold[gj], g_r[gj]);
        }
    }
    __syncthreads();

    int lane = tx & 31;
    int w    = tx >> 5;                  // warp 0..7, rows w*16 .. w*16+15

    float4 pj4 = reinterpret_cast<const float4*>(spj)[lane];  // cols 4*lane..+3
    float4 colacc = make_float4(0.0f, 0.0f, 0.0f, 0.0f);

    const float* base = M + (size_t)(bi * TILE) * n + bj * TILE;

    #pragma unroll 4
    for (int rr = 0; rr < 16; ++rr) {
        int la = w * 16 + rr;
        float4 m = __ldcs(reinterpret_cast<const float4*>(base + (size_t)la * n) + lane);
        // row contribution: dot(T[la][:], p_j)
        float rd = m.x * pj4.x + m.y * pj4.y + m.z * pj4.z + m.w * pj4.w;
        rd = warp_reduce(rd);
        if (lane == 0) yi[la] = rd;
        // column contribution: colacc[b] += T[la][b] * p_i[la]
        float pia = spi[la];
        colacc.x = fmaf(m.x, pia, colacc.x);
        colacc.y = fmaf(m.y, pia, colacc.y);
        colacc.z = fmaf(m.z, pia, colacc.z);
        colacc.w = fmaf(m.w, pia, colacc.w);
    }
    *reinterpret_cast<float4*>(&wcol[w][lane * 4]) = colacc;
    __syncthreads();

    if (tx < TILE) {
        atomicAdd(&g_Ap[bi * TILE + tx], yi[tx]);
    } else if (bi != bj) {               // diagonal: row pass already covers tile
        int b = tx - TILE;
        float s = 0.0f;
        #pragma unroll
        for (int ww = 0; ww < 8; ++ww) s += wcol[ww][b];
        atomicAdd(&g_Ap[bj * TILE + b], s);
    }
}

// pAp[it] = p . Ap   (8 blocks x 256 threads, one float4 each)
__global__ void __launch_bounds__(256) k_dot(int it) {
    float rtr = g_rTr[it];
    if (rtr <= CG_TOL) return;
    const float4* P4 = reinterpret_cast<const float4*>(pbuf(it & 1));
    const float4* A4 = reinterpret_cast<const float4*>(g_Ap);
    int q = blockIdx.x * 256 + threadIdx.x;
    float4 p = P4[q];
    float4 a = A4[q];
    float v = p.x * a.x + p.y * a.y + p.z * a.z + p.w * a.w;
    float s = block_reduce(v);
    if (threadIdx.x == 0) atomicAdd(&g_pAp[it], s);
}

// X += alpha p ; r -= alpha Ap ; rTr[it+1] += ||r_new||^2 ; Ap = 0 (for next it)
__global__ void __launch_bounds__(256) k_update(int n, int it) {
    float rtr = g_rTr[it];
    if (rtr <= CG_TOL) return;          // frozen: rTr[it+1] stays 0 -> stays frozen

    float alpha = rtr / g_pAp[it];
    const float4* P4 = reinterpret_cast<const float4*>(pbuf(it & 1));
    float4* AP4 = reinterpret_cast<float4*>(g_Ap);
    float4* R4  = reinterpret_cast<float4*>(g_r);
    float4* X4  = reinterpret_cast<float4*>(g_X);

    int q = blockIdx.x * 256 + threadIdx.x;   // 0..2047

    float4 p = P4[q];
    float4 a = AP4[q];
    float4 r = R4[q];
    float4 x = X4[q];

    x.x = fmaf(alpha, p.x, x.x); x.y = fmaf(alpha, p.y, x.y);
    x.z = fmaf(alpha, p.z, x.z); x.w = fmaf(alpha, p.w, x.w);
    X4[q] = x;

    r.x = fmaf(-alpha, a.x, r.x); r.y = fmaf(-alpha, a.y, r.y);
    r.z = fmaf(-alpha, a.z, r.z); r.w = fmaf(-alpha, a.w, r.w);
    R4[q] = r;

    AP4[q] = make_float4(0.0f, 0.0f, 0.0f, 0.0f);  // ready for next matvec

    float v = r.x*r.x + r.y*r.y + r.z*r.z + r.w*r.w;
    float s = block_reduce(v);
    if (threadIdx.x == 0) atomicAdd(&g_rTr[it + 1], s);
}

__global__ void k_writeback(float* __restrict__ out, int n) {
    int i = blockIdx.x * blockDim.x + threadIdx.x;
    if (i < n) out[i] = g_X[i];
}

extern "C" void kernel_launch(void* const* d_in, const int* in_sizes, int n_in,
                              void* d_out, int out_size) {
    // metadata order: X [n], M [n*n], RHS [n]
    const float* M   = (const float*)d_in[1];
    const float* RHS = (const float*)d_in[2];
    float* out = (float*)d_out;
    int n = in_sizes[0];

    const int T = 256;
    int vb = (n + T - 1) / T;

    k_init_vecs<<<vb, T>>>(RHS, n);

    int nblk = n / TILE;                          // 64
    int tri_blocks = nblk * (nblk + 1) / 2;       // 2080 lower tiles
    int up_blocks = (n / 4) / 256;                // 8 blocks
    for (int it = 0; it < CG_NITER; ++it) {
        k_matvec_sym<<<tri_blocks, 256>>>(M, n, it);
        k_dot<<<up_blocks, 256>>>(it);
        k_update<<<up_blocks, 256>>>(n, it);
    }
    k_writeback<<<vb, T>>>(out, n);
}

// round 17
// speedup vs baseline: 1.6969x; 1.0044x over previous
#include <cuda_runtime.h>
#include <cuda_bf16.h>

// CG solve via SYMMETRIC matvec: M = A A^T + I is symmetric, so Ap = M p is
// computed from the lower-triangular tiles only -> 53% of the matrix traffic.
// n = 8192, 64x64 grid of 128x128 tiles, 2080 lower tiles.
//
// Per iteration (3 launches):
//   k_matvec_sym: stages p_it = r + beta*p_old slices per block (diag blocks
//                 persist p_it), streams lower tiles; each off-diag tile adds
//                 both T*p_bj (rows) and T^T*p_bi (cols) into g_Ap via atomics.
//   k_dot:        pAp[it] = p . Ap   (8 blocks, exact sum via atomics)
//   k_update:     X += alpha p ; r -= alpha Ap ; rTr[it+1] = ||r_new||^2 ;
//                 zeroes g_Ap for the next iteration.

#define N_MAX 8192
#define TILE 128
#define NBLK (N_MAX / TILE)             // 64 block-rows
#define CG_NITER 20
#define CG_TOL 1e-10f

// ---- persistent device state (allocation-free scratch) ----
__device__ float g_X[N_MAX];
__device__ float g_r[N_MAX];
__device__ float g_p0[N_MAX];           // p parity buffers: p_it lives in (it&1)
__device__ float g_p1[N_MAX];
__device__ float g_Ap[N_MAX];           // zeroed before each matvec
__device__ float g_rTr[CG_NITER + 1];   // exact ||r||^2 entering iteration it
__device__ float g_pAp[CG_NITER];

__device__ __forceinline__ float* pbuf(int parity) { return parity ? g_p1 : g_p0; }

// ---- reductions ----
__device__ __forceinline__ float warp_reduce(float v) {
    #pragma unroll
    for (int o = 16; o > 0; o >>= 1) v += __shfl_xor_sync(0xffffffffu, v, o);
    return v;
}

__device__ __forceinline__ float block_reduce(float v) {
    __shared__ float sbuf[32];
    int lane = threadIdx.x & 31;
    int wid  = threadIdx.x >> 5;
    v = warp_reduce(v);
    if (lane == 0) sbuf[wid] = v;
    __syncthreads();
    int nw = (blockDim.x + 31) >> 5;
    v = (threadIdx.x < nw) ? sbuf[threadIdx.x] : 0.0f;
    if (wid == 0) v = warp_reduce(v);
    return v;
}

// ---- kernels ----

// X0 = 0, r0 = RHS, Ap = 0, rTr[0] = sum(RHS^2); zero scalar accumulators.
__global__ void k_init_vecs(const float* __restrict__ RHS, int n) {
    int i = blockIdx.x * blockDim.x + threadIdx.x;
    if (blockIdx.x == 0 && threadIdx.x < CG_NITER + 1) {
        g_rTr[threadIdx.x] = 0.0f;
        if (threadIdx.x < CG_NITER) g_pAp[threadIdx.x] = 0.0f;
    }
    float v = 0.0f;
    if (i < n) {
        float rhs = RHS[i];
        g_X[i] = 0.0f;
        g_r[i] = rhs;
        g_Ap[i] = 0.0f;
        v = rhs * rhs;
    }
    float s = block_reduce(v);
    if (threadIdx.x == 0) atomicAdd(&g_rTr[0], s);
}

// Symmetric tiled matvec. One block = one 128x128 tile (bi >= bj).
// 256 threads = 8 warps x 16 rows; one warp-LDG.128 covers a full 512B row.
__global__ void __launch_bounds__(256) k_matvec_sym(const float* __restrict__ M, int n, int it) {
    float rtr = g_rTr[it];
    if (rtr <= CG_TOL) return;          // frozen: skip everything

    // decode lower-triangle tile (bi, bj), t = bi*(bi+1)/2 + bj
    int t = blockIdx.x;
    int bi = (int)((sqrtf(8.0f * (float)t + 1.0f) - 1.0f) * 0.5f);
    while ((bi + 1) * (bi + 2) / 2 <= t) bi++;
    while (bi * (bi + 1) / 2 > t) bi--;
    int bj = t - bi * (bi + 1) / 2;

    __shared__ float spi[TILE];          // p slice for block-row bi
    __shared__ float spj[TILE];          // p slice for block-col bj
    __shared__ float yi[TILE];           // row-dot results
    __shared__ float wcol[8][TILE];      // per-warp column partials

    int tx = threadIdx.x;

    // stage p_it = r + beta * p_old for the two slices this tile needs
    {
        float beta = (it == 0) ? 0.0f : rtr / g_rTr[it - 1];
        const float* pold = pbuf((it - 1) & 1);
        if (tx < TILE) {
            int gi = bi * TILE + tx;
            float v = (it == 0) ? g_r[gi] : fmaf(beta, pold[gi], g_r[gi]);
            spi[tx] = v;
            if (bi == bj) pbuf(it & 1)[gi] = v;   // diagonal blocks persist p_it
        } else {
            int j = tx - TILE;
            int gj = bj * TILE + j;
            spj[j] = (it == 0) ? g_r[gj] : fmaf(beta, pold[gj], g_r[gj]);
        }
    }
    __syncthreads();

    int lane = tx & 31;
    int w    = tx >> 5;                  // warp 0..7, rows w*16 .. w*16+15

    float4 pj4 = reinterpret_cast<const float4*>(spj)[lane];  // cols 4*lane..+3
    float4 colacc = make_float4(0.0f, 0.0f, 0.0f, 0.0f);

    const float* base = M + (size_t)(bi * TILE) * n + bj * TILE;

    #pragma unroll 4
    for (int rr = 0; rr < 16; ++rr) {
        int la = w * 16 + rr;
        float4 m = __ldcs(reinterpret_cast<const float4*>(base + (size_t)la * n) + lane);
        // row contribution: dot(T[la][:], p_j)
        float rd = m.x * pj4.x + m.y * pj4.y + m.z * pj4.z + m.w * pj4.w;
        rd = warp_reduce(rd);
        if (lane == 0) yi[la] = rd;
        // column contribution: colacc[b] += T[la][b] * p_i[la]
        float pia = spi[la];
        colacc.x = fmaf(m.x, pia, colacc.x);
        colacc.y = fmaf(m.y, pia, colacc.y);
        colacc.z = fmaf(m.z, pia, colacc.z);
        colacc.w = fmaf(m.w, pia, colacc.w);
    }
    *reinterpret_cast<float4*>(&wcol[w][lane * 4]) = colacc;
    __syncthreads();

    if (tx < TILE) {
        atomicAdd(&g_Ap[bi * TILE + tx], yi[tx]);
    } else if (bi != bj) {               // diagonal: row pass already covers tile
        int b = tx - TILE;
        float s = 0.0f;
        #pragma unroll
        for (int ww = 0; ww < 8; ++ww) s += wcol[ww][b];
        atomicAdd(&g_Ap[bj * TILE + b], s);
    }
}

// pAp[it] = p . Ap   (8 blocks x 256 threads, one float4 each)
__global__ void __launch_bounds__(256) k_dot(int it) {
    float rtr = g_rTr[it];
    if (rtr <= CG_TOL) return;
    const float4* P4 = reinterpret_cast<const float4*>(pbuf(it & 1));
    const float4* A4 = reinterpret_cast<const float4*>(g_Ap);
    int q = blockIdx.x * 256 + threadIdx.x;
    float4 p = P4[q];
    float4 a = A4[q];
    float v = p.x * a.x + p.y * a.y + p.z * a.z + p.w * a.w;
    float s = block_reduce(v);
    if (threadIdx.x == 0) atomicAdd(&g_pAp[it], s);
}

// X += alpha p ; r -= alpha Ap ; rTr[it+1] += ||r_new||^2 ; Ap = 0 (for next it)
__global__ void __launch_bounds__(256) k_update(int n, int it) {
    float rtr = g_rTr[it];
    if (rtr <= CG_TOL) return;          // frozen: rTr[it+1] stays 0 -> stays frozen

    float alpha = rtr / g_pAp[it];
    const float4* P4 = reinterpret_cast<const float4*>(pbuf(it & 1));
    float4* AP4 = reinterpret_cast<float4*>(g_Ap);
    float4* R4  = reinterpret_cast<float4*>(g_r);
    float4* X4  = reinterpret_cast<float4*>(g_X);

    int q = blockIdx.x * 256 + threadIdx.x;   // 0..2047

    float4 p = P4[q];
    float4 a = AP4[q];
    float4 r = R4[q];
    float4 x = X4[q];

    x.x = fmaf(alpha, p.x, x.x); x.y = fmaf(alpha, p.y, x.y);
    x.z = fmaf(alpha, p.z, x.z); x.w = fmaf(alpha, p.w, x.w);
    X4[q] = x;

    r.x = fmaf(-alpha, a.x, r.x); r.y = fmaf(-alpha, a.y, r.y);
    r.z = fmaf(-alpha, a.z, r.z); r.w = fmaf(-alpha, a.w, r.w);
    R4[q] = r;

    AP4[q] = make_float4(0.0f, 0.0f, 0.0f, 0.0f);  // ready for next matvec

    float v = r.x*r.x + r.y*r.y + r.z*r.z + r.w*r.w;
    float s = block_reduce(v);
    if (threadIdx.x == 0) atomicAdd(&g_rTr[it + 1], s);
}

__global__ void k_writeback(float* __restrict__ out, int n) {
    int i = blockIdx.x * blockDim.x + threadIdx.x;
    if (i < n) out[i] = g_X[i];
}

extern "C" void kernel_launch(void* const* d_in, const int* in_sizes, int n_in,
                              void* d_out, int out_size) {
    // metadata order: X [n], M [n*n], RHS [n]
    const float* M   = (const float*)d_in[1];
    const float* RHS = (const float*)d_in[2];
    float* out = (float*)d_out;
    int n = in_sizes[0];

    const int T = 256;
    int vb = (n + T - 1) / T;

    k_init_vecs<<<vb, T>>>(RHS, n);

    int nblk = n / TILE;                          // 64
    int tri_blocks = nblk * (nblk + 1) / 2;       // 2080 lower tiles
    int up_blocks = (n / 4) / 256;                // 8 blocks
    for (int it = 0; it < CG_NITER; ++it) {
        k_matvec_sym<<<tri_blocks, 256>>>(M, n, it);
        k_dot<<<up_blocks, 256>>>(it);
        k_update<<<up_blocks, 256>>>(n, it);
    }
    k_writeback<<<vb, T>>>(out, n);
}